// round 9
// baseline (speedup 1.0000x reference)
#include <cuda_runtime.h>

#define KK    64
#define S1C   5
#define CC    128
#define MM    320         // KK*S1C
#define PP    1936        // 44*44
#define NN    8
#define PT    128         // pixels per tile
#define TILES 16          // ceil(1936/128)
#define NBLK  128         // grid size (must be fully co-resident: 128 < 148 SMs)
#define ALPHA_C 1500.0f
#define EPS_C   1e-12f

// ---- device scratch (static: no allocations allowed) ----
__device__ float g_part[NN * TILES * KK * CC];  // per-tile partial accumulators (4.2 MB)
__device__ float g_sumw[NN * TILES * KK];
__device__ float g_rowss[NN * 8];               // per-(n, k-seg) row-norm partial sums
__device__ int g_arrive;                        // barrier arrival counter (resets to 0 each pass)
__device__ volatile int g_sense;                // sense flag (2 toggles per launch -> back to 0)

// ---- f32x2 helpers (ptxas never auto-emits FFMA2; B300 fma pipe is 2x wider via f32x2) ----
__device__ __forceinline__ unsigned long long dup2(float v) {
    unsigned long long r;
    asm("mov.b64 %0, {%1, %1};" : "=l"(r) : "f"(v));
    return r;
}
__device__ __forceinline__ void fma2(unsigned long long& d, unsigned long long a, unsigned long long b) {
    asm("fma.rn.f32x2 %0, %1, %2, %0;" : "+l"(d) : "l"(a), "l"(b));
}
__device__ __forceinline__ float2 unpack2(unsigned long long v) {
    float2 r;
    asm("mov.b64 {%0, %1}, %2;" : "=f"(r.x), "=f"(r.y) : "l"(v));
    return r;
}

// ---- device-wide sense-reversing barrier (all NBLK blocks co-resident) ----
__device__ __forceinline__ void gbar(int tid, int sense) {
    __syncthreads();
    if (tid == 0) {
        __threadfence();
        if (atomicAdd(&g_arrive, 1) == NBLK - 1) {
            g_arrive = 0;
            __threadfence();
            g_sense = 1 - sense;
        } else {
            while (g_sense == sense) __nanosleep(64);
        }
        __threadfence();
    }
    __syncthreads();
}

// ======================= single fused kernel =======================
// block = (n, pixel-tile of 128), 128 blocks = 1 co-resident wave. smem 158464 B:
//   xs : [64 c2][130 p][2]  pairs {x[2c2][p], x[2c2+1][p]}    66560 B
//   ws : 80 pairs x 256     one 80 KB w chunk / was alias     81920 B
//   red: [128 p][17]        cross-warp alpha reduction         8704 B
//   bs : float[320]         biases                             1280 B
__global__ __launch_bounds__(512, 1)
void main_kernel(const float* __restrict__ x, const float* __restrict__ cent,
                 float* __restrict__ sa_out, float* __restrict__ out) {
    extern __shared__ float smem[];
    float* xs  = smem;                    // 16640 floats
    float* ws  = smem + 16640;            // 20480 floats (alias: was 64x130x2 = 16640)
    float* red = smem + 16640 + 20480;    // 2176 floats
    float* bs  = red + 2176;              // 320 floats
    float* was = ws;

    int tid = threadIdx.x;
    int lane = tid & 31;    // pixel quad base p = 4*lane
    int mg = tid >> 5;      // warp id = k-pair base within chunk
    int bx = blockIdx.x;
    int n = bx >> 4, tile = bx & 15;
    int p0 = tile * PT;
    int pvalid = min(PT, PP - p0);   // 128, or 16 on tile 15 (multiple of 16)

    // ---- biases: warp per row, 20 rows per warp ----
    {
        for (int i = 0; i < 20; i++) {
            int r = mg * 20 + i;
            int ch = r / 160, rem = r - ch * 160;
            int j = rem / 80, rem2 = rem - j * 80;
            int s = rem2 >> 4, kmg = rem2 & 15;
            const float* cr = cent + ((32 * ch + kmg + 16 * j) * S1C + s) * CC;
            float a0 = cr[lane], a1 = cr[lane + 32], a2 = cr[lane + 64], a3 = cr[lane + 96];
            float ssq = a0 * a0 + a1 * a1 + a2 * a2 + a3 * a3;
            #pragma unroll
            for (int o = 16; o; o >>= 1) ssq += __shfl_xor_sync(0xffffffffu, ssq, o);
            if (lane == 0) bs[(ch * 80 + s * 16 + kmg) * 2 + j] = -ALPHA_C * sqrtf(ssq);
        }
    }

    // ---- load x tile: pair-interleave in registers, STS.128 stores ----
    {
        int r = tid >> 3;            // c2 row (64 rows)
        int seg = (tid & 7) * 16;    // pixel segment
        const float* s0 = x + (n * CC + 2 * r) * PP + p0 + seg;
        const float* s1 = s0 + PP;
        bool ok = seg < pvalid;
        #pragma unroll
        for (int i = 0; i < 4; i++) {
            float4 a = ok ? *(const float4*)(s0 + i * 4) : make_float4(0.f, 0.f, 0.f, 0.f);
            float4 b = ok ? *(const float4*)(s1 + i * 4) : make_float4(0.f, 0.f, 0.f, 0.f);
            float* d = xs + (r * 130 + seg + i * 4) * 2;
            *(float4*)(d)     = make_float4(a.x, b.x, a.y, b.y);
            *(float4*)(d + 4) = make_float4(a.z, b.z, a.w, b.w);
        }
    }

    // ---- phase 1: logits GEMM (2 chunks of 32 k x 5 s) + register softmax over s ----
    float l0r[16], btr[16];   // idx = ch*8 + k2*4 + px ; k = ch*32 + mg + k2*16
    for (int ch = 0; ch < 2; ch++) {
        __syncthreads();
        {   // build w chunk from centroids (L2-resident): warp handles 5 P rows
            #pragma unroll
            for (int i = 0; i < 5; i++) {
                int P = mg * 5 + i;           // 0..79
                int s = P >> 4, kmg = P & 15;
                const float* c0p = cent + ((32 * ch + kmg) * S1C + s) * CC;
                const float* c1p = c0p + 80 * CC;   // k+16 -> m+80
                #pragma unroll
                for (int u = 0; u < 4; u++) {
                    int c = lane + 32 * u;
                    *(float2*)(ws + P * 256 + c * 2) =
                        make_float2(2.0f * ALPHA_C * c0p[c], 2.0f * ALPHA_C * c1p[c]);
                }
            }
        }
        __syncthreads();

        unsigned long long acc[5][4];
        #pragma unroll
        for (int s = 0; s < 5; s++)
            #pragma unroll
            for (int q = 0; q < 4; q++) acc[s][q] = 0ull;

        #pragma unroll 4
        for (int c2 = 0; c2 < 64; c2++) {
            const float* xr = xs + (c2 * 130 + 4 * lane) * 2;
            float4 xa = *(const float4*)xr;
            float4 xb = *(const float4*)(xr + 4);
            unsigned long long xd0 = dup2(xa.x), xd1 = dup2(xa.y);
            unsigned long long xd2 = dup2(xa.z), xd3 = dup2(xa.w);
            unsigned long long xd4 = dup2(xb.x), xd5 = dup2(xb.y);
            unsigned long long xd6 = dup2(xb.z), xd7 = dup2(xb.w);
            #pragma unroll
            for (int s = 0; s < 5; s++) {
                ulonglong2 wv = *(const ulonglong2*)(ws + (s * 16 + mg) * 256 + c2 * 4);
                fma2(acc[s][0], wv.x, xd0); fma2(acc[s][0], wv.y, xd1);
                fma2(acc[s][1], wv.x, xd2); fma2(acc[s][1], wv.y, xd3);
                fma2(acc[s][2], wv.x, xd4); fma2(acc[s][2], wv.y, xd5);
                fma2(acc[s][3], wv.x, xd6); fma2(acc[s][3], wv.y, xd7);
            }
        }

        float b0[5], b1[5];
        #pragma unroll
        for (int s = 0; s < 5; s++) {
            b0[s] = bs[(ch * 80 + s * 16 + mg) * 2 + 0];
            b1[s] = bs[(ch * 80 + s * 16 + mg) * 2 + 1];
        }
        #pragma unroll
        for (int px = 0; px < 4; px++) {
            float lx[5], ly[5];
            #pragma unroll
            for (int s = 0; s < 5; s++) {
                float2 a = unpack2(acc[s][px]);
                lx[s] = a.x + b0[s];
                ly[s] = a.y + b1[s];
            }
            float m0 = fmaxf(fmaxf(fmaxf(lx[0], lx[1]), fmaxf(lx[2], lx[3])), lx[4]);
            float e0 = __expf(lx[0] - m0);
            float s0 = e0 + __expf(lx[1] - m0) + __expf(lx[2] - m0)
                          + __expf(lx[3] - m0) + __expf(lx[4] - m0);
            l0r[ch * 8 + px] = lx[0];
            btr[ch * 8 + px] = e0 * __frcp_rn(s0);
            float m1 = fmaxf(fmaxf(fmaxf(ly[0], ly[1]), fmaxf(ly[2], ly[3])), ly[4]);
            float e1 = __expf(ly[0] - m1);
            float s1 = e1 + __expf(ly[1] - m1) + __expf(ly[2] - m1)
                          + __expf(ly[3] - m1) + __expf(ly[4] - m1);
            l0r[ch * 8 + 4 + px] = ly[0];
            btr[ch * 8 + 4 + px] = e1 * __frcp_rn(s1);
        }
    }

    // ---- alpha softmax over k: cross-warp reduction via red[p][17] ----
    #pragma unroll
    for (int px = 0; px < 4; px++) {
        float mx = fmaxf(fmaxf(l0r[px], l0r[4 + px]), fmaxf(l0r[8 + px], l0r[12 + px]));
        red[(4 * lane + px) * 17 + mg] = mx;
    }
    __syncthreads();
    float amax[4];
    #pragma unroll
    for (int px = 0; px < 4; px++) {
        float m = -1e30f;
        #pragma unroll
        for (int i = 0; i < 16; i++) m = fmaxf(m, red[(4 * lane + px) * 17 + i]);
        amax[px] = m;
    }
    __syncthreads();
    #pragma unroll
    for (int px = 0; px < 4; px++) {
        float s = __expf(l0r[px] - amax[px]) + __expf(l0r[4 + px] - amax[px])
                + __expf(l0r[8 + px] - amax[px]) + __expf(l0r[12 + px] - amax[px]);
        red[(4 * lane + px) * 17 + mg] = s;
    }
    __syncthreads();
    float ainv[4];
    #pragma unroll
    for (int px = 0; px < 4; px++) {
        float s = 0.f;
        #pragma unroll
        for (int i = 0; i < 16; i++) s += red[(4 * lane + px) * 17 + i];
        ainv[px] = __frcp_rn(s);
    }

    // ---- w_assign to smem (alias over ws), soft_assign to gmem, sumw ----
    #pragma unroll
    for (int ch = 0; ch < 2; ch++)
        #pragma unroll
        for (int k2 = 0; k2 < 2; k2++) {
            int k = ch * 32 + mg + k2 * 16;
            float sav[4];
            float sw = 0.f;
            #pragma unroll
            for (int px = 0; px < 4; px++) {
                int idx = ch * 8 + k2 * 4 + px;
                float sa = __expf(l0r[idx] - amax[px]) * ainv[px] * btr[idx];
                int p = 4 * lane + px;
                float wa = (p < pvalid) ? (1.0f + sa) : 0.0f;
                sav[px] = sa;
                sw += wa;
                *(float2*)(was + (k * 130 + p) * 2) = make_float2(wa, wa);
            }
            if (4 * lane < pvalid)
                *(float4*)(sa_out + (n * KK + k) * PP + p0 + 4 * lane) =
                    make_float4(sav[0], sav[1], sav[2], sav[3]);
            #pragma unroll
            for (int o = 16; o; o >>= 1) sw += __shfl_xor_sync(0xffffffffu, sw, o);
            if (lane == 0) g_sumw[bx * 64 + k] = sw;
        }
    __syncthreads();

    // ---- phase 2: out_part[k][c] = sum_p wa[k][p] * x[c][p] ----
    {
        int cg = lane, kg = mg;   // k = kg*4+q ; c2 = cg and cg+32
        unsigned long long a2[4][2];
        #pragma unroll
        for (int q = 0; q < 4; q++) { a2[q][0] = 0ull; a2[q][1] = 0ull; }
        #pragma unroll 2
        for (int p = 0; p < PT; p += 2) {
            ulonglong2 xv0 = *(const ulonglong2*)(xs + (cg * 130 + p) * 2);
            ulonglong2 xv1 = *(const ulonglong2*)(xs + ((cg + 32) * 130 + p) * 2);
            #pragma unroll
            for (int q = 0; q < 4; q++) {
                ulonglong2 wv = *(const ulonglong2*)(was + ((kg * 4 + q) * 130 + p) * 2);
                fma2(a2[q][0], wv.x, xv0.x);
                fma2(a2[q][0], wv.y, xv0.y);
                fma2(a2[q][1], wv.x, xv1.x);
                fma2(a2[q][1], wv.y, xv1.y);
            }
        }
        float* pb = g_part + bx * 8192;
        #pragma unroll
        for (int q = 0; q < 4; q++) {
            int k = kg * 4 + q;
            #pragma unroll
            for (int j = 0; j < 2; j++) {
                int c2 = cg + 32 * j;
                float2 r = unpack2(a2[q][j]);
                *(float2*)(pb + k * 128 + c2 * 2) = r;
            }
        }
    }

    // ================= device-wide barrier 1 =================
    gbar(tid, 0);

    // ---- finalize stage A (64 blocks): tile-reduce, -rep*sumw, row norm ----
    if (bx < 64) {
        int n2 = bx >> 3, seg = bx & 7;
        int kl = tid >> 6, ci = tid & 63;
        int k = seg * 8 + kl, c0 = ci * 2;
        const float* pb = g_part + n2 * TILES * 8192 + k * 128 + c0;
        float a0 = 0.f, a1 = 0.f;
        #pragma unroll
        for (int t = 0; t < TILES; t++) {
            float2 u = *(const float2*)(pb + t * 8192);
            a0 += u.x; a1 += u.y;
        }
        float sw = 0.f;
        const float* sb = g_sumw + n2 * TILES * 64 + k;
        #pragma unroll
        for (int t = 0; t < TILES; t++) sw += sb[t * 64];
        float2 rp = *(const float2*)(cent + k * (S1C * CC) + c0);
        float v0 = a0 - rp.x * sw;
        float v1 = a1 - rp.y * sw;
        float ssq = v0 * v0 + v1 * v1;
        #pragma unroll
        for (int o = 16; o; o >>= 1) ssq += __shfl_xor_sync(0xffffffffu, ssq, o);
        if ((tid & 31) == 0) red[kl * 2 + ((tid >> 5) & 1)] = ssq;
        __syncthreads();
        if (tid < 8) {
            float t2 = red[tid * 2] + red[tid * 2 + 1];
            float rn = fmaxf(sqrtf(t2), EPS_C);
            red[16 + tid] = rn;
            red[32 + tid] = t2 / (rn * rn);
        }
        __syncthreads();
        if (tid == 0) {
            float s = 0.f;
            #pragma unroll
            for (int i = 0; i < 8; i++) s += red[32 + i];
            g_rowss[n2 * 8 + seg] = s;
        }
        float rn = red[16 + kl];
        float* vt = g_part + n2 * TILES * 8192 + k * 128 + c0;  // tile-0 slot reuse
        *(float2*)vt = make_float2(v0 / rn, v1 / rn);
    }

    // ================= device-wide barrier 2 =================
    gbar(tid, 1);

    // ---- finalize stage B (64 blocks): global norm per n, write flat ----
    if (bx < 64) {
        int n2 = bx >> 3, seg = bx & 7;
        float tot = 0.f;
        #pragma unroll
        for (int u = 0; u < 8; u++) tot += g_rowss[n2 * 8 + u];
        float sc = 1.0f / fmaxf(sqrtf(tot), EPS_C);
        int kl = tid >> 6, ci = tid & 63;
        int k = seg * 8 + kl, c0 = ci * 2;
        float2 v = *(const float2*)(g_part + n2 * TILES * 8192 + k * 128 + c0);
        *(float2*)(out + n2 * (KK * CC) + k * 128 + c0) = make_float2(v.x * sc, v.y * sc);
    }
}

extern "C" void kernel_launch(void* const* d_in, const int* in_sizes, int n_in,
                              void* d_out, int out_size) {
    const float* x    = (const float*)d_in[0];   // (8,128,44,44)
    const float* cent = (const float*)d_in[1];   // (64,5,128)
    float* out = (float*)d_out;                  // [flat (8,8192) | soft_assign (8,64,1,1936)]
    float* sa = out + NN * KK * CC;

    cudaFuncSetAttribute(main_kernel, cudaFuncAttributeMaxDynamicSharedMemorySize, 158464);
    main_kernel<<<NBLK, 512, 158464>>>(x, cent, sa, out);
}

// round 10
// speedup vs baseline: 1.1409x; 1.1409x over previous
#include <cuda_runtime.h>

#define KK    64
#define S1C   5
#define CC    128
#define MM    320         // KK*S1C
#define PP    1936        // 44*44
#define NN    8
#define PT    128         // pixels per tile
#define TILES 16          // ceil(1936/128)
#define NBLK  128         // grid size (fully co-resident: 128 < 148 SMs)
#define ALPHA_C 1500.0f
#define EPS_C   1e-12f

// ---- device scratch (static: no allocations allowed) ----
__device__ float g_part[NN * TILES * KK * CC];  // per-tile partial accumulators (4.2 MB)
__device__ float g_sumw[NN * TILES * KK];
__device__ float g_rowss[NN * 8];               // per-(n, k-seg) row-norm partial sums
__device__ int g_cnt[NN];                       // per-n progress: 16 tiles -> 24 stageA -> 32 stageB -> reset 0

// ---- f32x2 helpers (ptxas never auto-emits FFMA2; B300 fma pipe is 2x wider via f32x2) ----
__device__ __forceinline__ unsigned long long dup2(float v) {
    unsigned long long r;
    asm("mov.b64 %0, {%1, %1};" : "=l"(r) : "f"(v));
    return r;
}
__device__ __forceinline__ void fma2(unsigned long long& d, unsigned long long a, unsigned long long b) {
    asm("fma.rn.f32x2 %0, %1, %2, %0;" : "+l"(d) : "l"(a), "l"(b));
}
__device__ __forceinline__ float2 unpack2(unsigned long long v) {
    float2 r;
    asm("mov.b64 {%0, %1}, %2;" : "=f"(r.x), "=f"(r.y) : "l"(v));
    return r;
}

// ======================= single fused kernel =======================
// block = (n, pixel-tile of 128), 128 blocks = 1 co-resident wave. smem 158464 B:
//   xs : [64 c2][130 p][2]  pairs {x[2c2][p], x[2c2+1][p]}    66560 B
//   ws : 80 pairs x 256     one 80 KB w chunk / was alias     81920 B
//   red: [128 p][17]        cross-warp alpha reduction         8704 B
//   bs : float[320]         biases                             1280 B
__global__ __launch_bounds__(512, 1)
void main_kernel(const float* __restrict__ x, const float* __restrict__ cent,
                 float* __restrict__ sa_out, float* __restrict__ out) {
    extern __shared__ float smem[];
    float* xs  = smem;                    // 16640 floats
    float* ws  = smem + 16640;            // 20480 floats (alias: was 64x130x2 = 16640)
    float* red = smem + 16640 + 20480;    // 2176 floats
    float* bs  = red + 2176;              // 320 floats
    float* was = ws;

    int tid = threadIdx.x;
    int lane = tid & 31;    // pixel quad base p = 4*lane
    int mg = tid >> 5;      // warp id = k-pair base within chunk
    int bx = blockIdx.x;
    int n = bx >> 4, tile = bx & 15;
    int p0 = tile * PT;
    int pvalid = min(PT, PP - p0);   // 128, or 16 on tile 15 (multiple of 16)

    // ---- load x tile: pair-interleave in registers, STS.128 stores ----
    {
        int r = tid >> 3;            // c2 row (64 rows)
        int seg = (tid & 7) * 16;    // pixel segment
        const float* s0 = x + (n * CC + 2 * r) * PP + p0 + seg;
        const float* s1 = s0 + PP;
        bool ok = seg < pvalid;
        #pragma unroll
        for (int i = 0; i < 4; i++) {
            float4 a = ok ? *(const float4*)(s0 + i * 4) : make_float4(0.f, 0.f, 0.f, 0.f);
            float4 b = ok ? *(const float4*)(s1 + i * 4) : make_float4(0.f, 0.f, 0.f, 0.f);
            float* d = xs + (r * 130 + seg + i * 4) * 2;
            *(float4*)(d)     = make_float4(a.x, b.x, a.y, b.y);
            *(float4*)(d + 4) = make_float4(a.z, b.z, a.w, b.w);
        }
    }

    // ---- phase 1: logits GEMM (2 chunks of 32 k x 5 s) + register softmax over s ----
    float l0r[16], btr[16];   // idx = ch*8 + k2*4 + px ; k = ch*32 + mg + k2*16
    for (int ch = 0; ch < 2; ch++) {
        __syncthreads();
        {   // build w chunk from centroids (L2-resident) + fold bias (ssq of same loads)
            #pragma unroll
            for (int i = 0; i < 5; i++) {
                int P = mg * 5 + i;           // row index = s*16 + kmg, 0..79
                int s = P >> 4, kmg = P & 15;
                const float* c0p = cent + ((32 * ch + kmg) * S1C + s) * CC;
                const float* c1p = c0p + 80 * CC;   // k+16
                float ssq0 = 0.f, ssq1 = 0.f;
                #pragma unroll
                for (int u = 0; u < 4; u++) {
                    int c = lane + 32 * u;
                    float a = c0p[c], b = c1p[c];
                    *(float2*)(ws + P * 256 + c * 2) =
                        make_float2(2.0f * ALPHA_C * a, 2.0f * ALPHA_C * b);
                    ssq0 += a * a;
                    ssq1 += b * b;
                }
                #pragma unroll
                for (int o = 16; o; o >>= 1) {
                    ssq0 += __shfl_xor_sync(0xffffffffu, ssq0, o);
                    ssq1 += __shfl_xor_sync(0xffffffffu, ssq1, o);
                }
                if (lane == 0) {
                    bs[(ch * 80 + P) * 2 + 0] = -ALPHA_C * sqrtf(ssq0);
                    bs[(ch * 80 + P) * 2 + 1] = -ALPHA_C * sqrtf(ssq1);
                }
            }
        }
        __syncthreads();

        unsigned long long acc[5][4];
        #pragma unroll
        for (int s = 0; s < 5; s++)
            #pragma unroll
            for (int q = 0; q < 4; q++) acc[s][q] = 0ull;

        #pragma unroll 4
        for (int c2 = 0; c2 < 64; c2++) {
            const float* xr = xs + (c2 * 130 + 4 * lane) * 2;
            float4 xa = *(const float4*)xr;
            float4 xb = *(const float4*)(xr + 4);
            unsigned long long xd0 = dup2(xa.x), xd1 = dup2(xa.y);
            unsigned long long xd2 = dup2(xa.z), xd3 = dup2(xa.w);
            unsigned long long xd4 = dup2(xb.x), xd5 = dup2(xb.y);
            unsigned long long xd6 = dup2(xb.z), xd7 = dup2(xb.w);
            #pragma unroll
            for (int s = 0; s < 5; s++) {
                ulonglong2 wv = *(const ulonglong2*)(ws + (s * 16 + mg) * 256 + c2 * 4);
                fma2(acc[s][0], wv.x, xd0); fma2(acc[s][0], wv.y, xd1);
                fma2(acc[s][1], wv.x, xd2); fma2(acc[s][1], wv.y, xd3);
                fma2(acc[s][2], wv.x, xd4); fma2(acc[s][2], wv.y, xd5);
                fma2(acc[s][3], wv.x, xd6); fma2(acc[s][3], wv.y, xd7);
            }
        }

        float b0[5], b1[5];
        #pragma unroll
        for (int s = 0; s < 5; s++) {
            b0[s] = bs[(ch * 80 + s * 16 + mg) * 2 + 0];
            b1[s] = bs[(ch * 80 + s * 16 + mg) * 2 + 1];
        }
        #pragma unroll
        for (int px = 0; px < 4; px++) {
            float lx[5], ly[5];
            #pragma unroll
            for (int s = 0; s < 5; s++) {
                float2 a = unpack2(acc[s][px]);
                lx[s] = a.x + b0[s];
                ly[s] = a.y + b1[s];
            }
            float m0 = fmaxf(fmaxf(fmaxf(lx[0], lx[1]), fmaxf(lx[2], lx[3])), lx[4]);
            float e0 = __expf(lx[0] - m0);
            float s0 = e0 + __expf(lx[1] - m0) + __expf(lx[2] - m0)
                          + __expf(lx[3] - m0) + __expf(lx[4] - m0);
            l0r[ch * 8 + px] = lx[0];
            btr[ch * 8 + px] = e0 * __frcp_rn(s0);
            float m1 = fmaxf(fmaxf(fmaxf(ly[0], ly[1]), fmaxf(ly[2], ly[3])), ly[4]);
            float e1 = __expf(ly[0] - m1);
            float s1 = e1 + __expf(ly[1] - m1) + __expf(ly[2] - m1)
                          + __expf(ly[3] - m1) + __expf(ly[4] - m1);
            l0r[ch * 8 + 4 + px] = ly[0];
            btr[ch * 8 + 4 + px] = e1 * __frcp_rn(s1);
        }
    }

    // ---- alpha softmax over k: cross-warp reduction via red[p][17] ----
    #pragma unroll
    for (int px = 0; px < 4; px++) {
        float mx = fmaxf(fmaxf(l0r[px], l0r[4 + px]), fmaxf(l0r[8 + px], l0r[12 + px]));
        red[(4 * lane + px) * 17 + mg] = mx;
    }
    __syncthreads();
    float amax[4];
    #pragma unroll
    for (int px = 0; px < 4; px++) {
        float m = -1e30f;
        #pragma unroll
        for (int i = 0; i < 16; i++) m = fmaxf(m, red[(4 * lane + px) * 17 + i]);
        amax[px] = m;
    }
    __syncthreads();
    #pragma unroll
    for (int px = 0; px < 4; px++) {
        float s = __expf(l0r[px] - amax[px]) + __expf(l0r[4 + px] - amax[px])
                + __expf(l0r[8 + px] - amax[px]) + __expf(l0r[12 + px] - amax[px]);
        red[(4 * lane + px) * 17 + mg] = s;
    }
    __syncthreads();
    float ainv[4];
    #pragma unroll
    for (int px = 0; px < 4; px++) {
        float s = 0.f;
        #pragma unroll
        for (int i = 0; i < 16; i++) s += red[(4 * lane + px) * 17 + i];
        ainv[px] = __frcp_rn(s);
    }

    // ---- w_assign to smem (alias over ws), soft_assign to gmem, sumw ----
    #pragma unroll
    for (int ch = 0; ch < 2; ch++)
        #pragma unroll
        for (int k2 = 0; k2 < 2; k2++) {
            int k = ch * 32 + mg + k2 * 16;
            float sav[4];
            float sw = 0.f;
            #pragma unroll
            for (int px = 0; px < 4; px++) {
                int idx = ch * 8 + k2 * 4 + px;
                float sa = __expf(l0r[idx] - amax[px]) * ainv[px] * btr[idx];
                int p = 4 * lane + px;
                float wa = (p < pvalid) ? (1.0f + sa) : 0.0f;
                sav[px] = sa;
                sw += wa;
                *(float2*)(was + (k * 130 + p) * 2) = make_float2(wa, wa);
            }
            if (4 * lane < pvalid)
                *(float4*)(sa_out + (n * KK + k) * PP + p0 + 4 * lane) =
                    make_float4(sav[0], sav[1], sav[2], sav[3]);
            #pragma unroll
            for (int o = 16; o; o >>= 1) sw += __shfl_xor_sync(0xffffffffu, sw, o);
            if (lane == 0) g_sumw[bx * 64 + k] = sw;
        }
    __syncthreads();

    // ---- phase 2: out_part[k][c] = sum_p wa[k][p] * x[c][p] ----
    {
        int cg = lane, kg = mg;   // k = kg*4+q ; c2 = cg and cg+32
        unsigned long long a2[4][2];
        #pragma unroll
        for (int q = 0; q < 4; q++) { a2[q][0] = 0ull; a2[q][1] = 0ull; }
        #pragma unroll 2
        for (int p = 0; p < PT; p += 2) {
            ulonglong2 xv0 = *(const ulonglong2*)(xs + (cg * 130 + p) * 2);
            ulonglong2 xv1 = *(const ulonglong2*)(xs + ((cg + 32) * 130 + p) * 2);
            #pragma unroll
            for (int q = 0; q < 4; q++) {
                ulonglong2 wv = *(const ulonglong2*)(was + ((kg * 4 + q) * 130 + p) * 2);
                fma2(a2[q][0], wv.x, xv0.x);
                fma2(a2[q][0], wv.y, xv0.y);
                fma2(a2[q][1], wv.x, xv1.x);
                fma2(a2[q][1], wv.y, xv1.y);
            }
        }
        float* pb = g_part + bx * 8192;
        #pragma unroll
        for (int q = 0; q < 4; q++) {
            int k = kg * 4 + q;
            #pragma unroll
            for (int j = 0; j < 2; j++) {
                int c2 = cg + 32 * j;
                float2 r = unpack2(a2[q][j]);
                *(float2*)(pb + k * 128 + c2 * 2) = r;
            }
        }
    }

    // ---- signal: this n's tile done (g_part + g_sumw visible) ----
    __syncthreads();
    if (tid == 0) {
        __threadfence();
        atomicAdd(&g_cnt[n], 1);
    }

    if (bx >= 64) return;   // non-worker blocks exit

    // ---- finalize stage A (64 blocks): wait for n2's 16 tiles, tile-reduce, row norm ----
    int n2 = bx >> 3, seg = bx & 7;
    if (tid == 0) {
        while (((volatile int*)g_cnt)[n2] < 16) __nanosleep(32);
        __threadfence();
    }
    __syncthreads();
    {
        int kl = tid >> 6, ci = tid & 63;
        int k = seg * 8 + kl, c0 = ci * 2;
        const float* pb = g_part + n2 * TILES * 8192 + k * 128 + c0;
        float a0 = 0.f, a1 = 0.f;
        #pragma unroll
        for (int t = 0; t < TILES; t++) {
            float2 u = *(const float2*)(pb + t * 8192);
            a0 += u.x; a1 += u.y;
        }
        float sw = 0.f;
        const float* sb = g_sumw + n2 * TILES * 64 + k;
        #pragma unroll
        for (int t = 0; t < TILES; t++) sw += sb[t * 64];
        float2 rp = *(const float2*)(cent + k * (S1C * CC) + c0);
        float v0 = a0 - rp.x * sw;
        float v1 = a1 - rp.y * sw;
        float ssq = v0 * v0 + v1 * v1;
        #pragma unroll
        for (int o = 16; o; o >>= 1) ssq += __shfl_xor_sync(0xffffffffu, ssq, o);
        if ((tid & 31) == 0) red[kl * 2 + ((tid >> 5) & 1)] = ssq;
        __syncthreads();
        if (tid < 8) {
            float t2 = red[tid * 2] + red[tid * 2 + 1];
            float rn = fmaxf(sqrtf(t2), EPS_C);
            red[16 + tid] = rn;
            red[32 + tid] = t2 / (rn * rn);
        }
        __syncthreads();
        if (tid == 0) {
            float s = 0.f;
            #pragma unroll
            for (int i = 0; i < 8; i++) s += red[32 + i];
            g_rowss[n2 * 8 + seg] = s;
        }
        float rn = red[16 + kl];
        float* vt = g_part + n2 * TILES * 8192 + k * 128 + c0;  // tile-0 slot reuse
        *(float2*)vt = make_float2(v0 / rn, v1 / rn);
    }
    __syncthreads();
    if (tid == 0) {
        __threadfence();
        atomicAdd(&g_cnt[n2], 1);     // -> 24 when all 8 stage-A done for n2
    }

    // ---- finalize stage B: wait for n2's 8 stage-A blocks, global norm, write flat ----
    if (tid == 0) {
        while (((volatile int*)g_cnt)[n2] < 24) __nanosleep(32);
        __threadfence();
    }
    __syncthreads();
    {
        float tot = 0.f;
        #pragma unroll
        for (int u = 0; u < 8; u++) tot += g_rowss[n2 * 8 + u];
        float sc = 1.0f / fmaxf(sqrtf(tot), EPS_C);
        int kl = tid >> 6, ci = tid & 63;
        int k = seg * 8 + kl, c0 = ci * 2;
        float2 v = *(const float2*)(g_part + n2 * TILES * 8192 + k * 128 + c0);
        *(float2*)(out + n2 * (KK * CC) + k * 128 + c0) = make_float2(v.x * sc, v.y * sc);
    }
    __syncthreads();
    if (tid == 0) {
        int old = atomicAdd(&g_cnt[n2], 1);   // -> 32 when all 8 stage-B done
        if (old == 31) {
            __threadfence();
            g_cnt[n2] = 0;                    // reset for next graph replay
        }
    }
}

extern "C" void kernel_launch(void* const* d_in, const int* in_sizes, int n_in,
                              void* d_out, int out_size) {
    const float* x    = (const float*)d_in[0];   // (8,128,44,44)
    const float* cent = (const float*)d_in[1];   // (64,5,128)
    float* out = (float*)d_out;                  // [flat (8,8192) | soft_assign (8,64,1,1936)]
    float* sa = out + NN * KK * CC;

    cudaFuncSetAttribute(main_kernel, cudaFuncAttributeMaxDynamicSharedMemorySize, 158464);
    main_kernel<<<NBLK, 512, 158464>>>(x, cent, sa, out);
}

// round 15
// speedup vs baseline: 1.1893x; 1.0425x over previous
#include <cuda_runtime.h>

#define KK    64
#define S1C   5
#define CC    128
#define MM    320         // KK*S1C
#define PP    1936        // 44*44
#define NN    8
#define PT    128         // pixels per tile
#define TILES 16          // ceil(1936/128)
#define NBLK  128         // grid size (fully co-resident: 128 < 148 SMs)
#define ALPHA_C 1500.0f
#define EPS_C   1e-12f

// ---- device scratch (static: no allocations allowed) ----
__device__ float g_part[NN * TILES * KK * CC];  // per-tile partial accumulators (4.2 MB)
__device__ float g_sumw[NN * TILES * KK];
__device__ int g_cnt[NN];                       // per-n progress: 16 tiles -> 24 stageA -> reset 0

// ---- f32x2 helpers (ptxas never auto-emits FFMA2) ----
__device__ __forceinline__ unsigned long long dup2(float v) {
    unsigned long long r;
    asm("mov.b64 %0, {%1, %1};" : "=l"(r) : "f"(v));
    return r;
}
__device__ __forceinline__ void fma2(unsigned long long& d, unsigned long long a, unsigned long long b) {
    asm("fma.rn.f32x2 %0, %1, %2, %0;" : "+l"(d) : "l"(a), "l"(b));
}
__device__ __forceinline__ float2 unpack2(unsigned long long v) {
    float2 r;
    asm("mov.b64 {%0, %1}, %2;" : "=f"(r.x), "=f"(r.y) : "l"(v));
    return r;
}

// ======================= single fused kernel =======================
// block = (n, pixel-tile of 128), 128 blocks = 1 co-resident wave. smem 158464 B:
//   xs : [64 c2][130 p][2]  pairs {x[2c2][p], x[2c2+1][p]}    66560 B
//   ws : 80 pairs x 256     one 80 KB w chunk / was alias     81920 B
//   red: [128 p][17]        cross-warp alpha reduction         8704 B
//   bs : float[320]         biases                             1280 B
__global__ __launch_bounds__(512, 1)
void main_kernel(const float* __restrict__ x, const float* __restrict__ cent,
                 float* __restrict__ sa_out, float* __restrict__ out) {
    extern __shared__ float smem[];
    float* xs  = smem;                    // 16640 floats
    float* ws  = smem + 16640;            // 20480 floats (alias: was 64x130x2 = 16640)
    float* red = smem + 16640 + 20480;    // 2176 floats
    float* bs  = red + 2176;              // 320 floats
    float* was = ws;

    int tid = threadIdx.x;
    int lane = tid & 31;
    int mg = tid >> 5;      // warp id = k-pair base within chunk
    int bx = blockIdx.x;
    int n = bx >> 4, tile = bx & 15;
    int p0 = tile * PT;
    int pvalid = min(PT, PP - p0);   // 128, or 16 on tile 15

    // this thread's 4 pixels (dense-LDS mapping): {2l, 2l+1, 64+2l, 65+2l}
    int pA = 2 * lane;        // pixels pA, pA+1  (streams px=0,1)
    int pB = 64 + 2 * lane;   // pixels pB, pB+1  (streams px=2,3)

    // ---- load x tile: pair-interleave in registers, STS.128 stores ----
    {
        int r = tid >> 3;            // c2 row (64 rows)
        int seg = (tid & 7) * 16;    // pixel segment
        const float* s0 = x + (n * CC + 2 * r) * PP + p0 + seg;
        const float* s1 = s0 + PP;
        bool ok = seg < pvalid;
        #pragma unroll
        for (int i = 0; i < 4; i++) {
            float4 a = ok ? *(const float4*)(s0 + i * 4) : make_float4(0.f, 0.f, 0.f, 0.f);
            float4 b = ok ? *(const float4*)(s1 + i * 4) : make_float4(0.f, 0.f, 0.f, 0.f);
            float* d = xs + (r * 130 + seg + i * 4) * 2;
            *(float4*)(d)     = make_float4(a.x, b.x, a.y, b.y);
            *(float4*)(d + 4) = make_float4(a.z, b.z, a.w, b.w);
        }
    }

    // ---- phase 1: logits GEMM (2 chunks of 32 k x 5 s) + register softmax over s ----
    float l0r[16], btr[16];   // idx = ch*8 + k2*4 + px ; k = ch*32 + mg + k2*16
    for (int ch = 0; ch < 2; ch++) {
        __syncthreads();
        {   // build w chunk from centroids (L2-resident) + fold bias (ssq of same loads)
            #pragma unroll
            for (int i = 0; i < 5; i++) {
                int P = mg * 5 + i;           // row index = s*16 + kmg, 0..79
                int s = P >> 4, kmg = P & 15;
                const float* c0p = cent + ((32 * ch + kmg) * S1C + s) * CC;
                const float* c1p = c0p + 80 * CC;   // k+16
                float ssq0 = 0.f, ssq1 = 0.f;
                #pragma unroll
                for (int u = 0; u < 4; u++) {
                    int c = lane + 32 * u;
                    float a = c0p[c], b = c1p[c];
                    *(float2*)(ws + P * 256 + c * 2) =
                        make_float2(2.0f * ALPHA_C * a, 2.0f * ALPHA_C * b);
                    ssq0 += a * a;
                    ssq1 += b * b;
                }
                #pragma unroll
                for (int o = 16; o; o >>= 1) {
                    ssq0 += __shfl_xor_sync(0xffffffffu, ssq0, o);
                    ssq1 += __shfl_xor_sync(0xffffffffu, ssq1, o);
                }
                if (lane == 0) {
                    bs[(ch * 80 + P) * 2 + 0] = -ALPHA_C * sqrtf(ssq0);
                    bs[(ch * 80 + P) * 2 + 1] = -ALPHA_C * sqrtf(ssq1);
                }
            }
        }
        __syncthreads();

        unsigned long long acc[5][4];
        #pragma unroll
        for (int s = 0; s < 5; s++)
            #pragma unroll
            for (int q = 0; q < 4; q++) acc[s][q] = 0ull;

        #pragma unroll 4
        for (int c2 = 0; c2 < 64; c2++) {
            // DENSE loads: lanes at 16-B stride (contiguous 512 B per warp per LDS.128)
            const float* xrow = xs + c2 * 260;  // (c2*130)*2
            float4 xa = *(const float4*)(xrow + 4 * lane);        // pixels 2l, 2l+1
            float4 xb = *(const float4*)(xrow + 128 + 4 * lane);  // pixels 64+2l, 65+2l
            unsigned long long xd0 = dup2(xa.x), xd1 = dup2(xa.y);   // px0: c even, odd
            unsigned long long xd2 = dup2(xa.z), xd3 = dup2(xa.w);   // px1
            unsigned long long xd4 = dup2(xb.x), xd5 = dup2(xb.y);   // px2
            unsigned long long xd6 = dup2(xb.z), xd7 = dup2(xb.w);   // px3
            #pragma unroll
            for (int s = 0; s < 5; s++) {
                ulonglong2 wv = *(const ulonglong2*)(ws + (s * 16 + mg) * 256 + c2 * 4);
                fma2(acc[s][0], wv.x, xd0); fma2(acc[s][0], wv.y, xd1);
                fma2(acc[s][1], wv.x, xd2); fma2(acc[s][1], wv.y, xd3);
                fma2(acc[s][2], wv.x, xd4); fma2(acc[s][2], wv.y, xd5);
                fma2(acc[s][3], wv.x, xd6); fma2(acc[s][3], wv.y, xd7);
            }
        }

        float b0[5], b1[5];
        #pragma unroll
        for (int s = 0; s < 5; s++) {
            b0[s] = bs[(ch * 80 + s * 16 + mg) * 2 + 0];
            b1[s] = bs[(ch * 80 + s * 16 + mg) * 2 + 1];
        }
        #pragma unroll
        for (int px = 0; px < 4; px++) {
            float lx[5], ly[5];
            #pragma unroll
            for (int s = 0; s < 5; s++) {
                float2 a = unpack2(acc[s][px]);
                lx[s] = a.x + b0[s];
                ly[s] = a.y + b1[s];
            }
            float m0 = fmaxf(fmaxf(fmaxf(lx[0], lx[1]), fmaxf(lx[2], lx[3])), lx[4]);
            float e0 = __expf(lx[0] - m0);
            float s0 = e0 + __expf(lx[1] - m0) + __expf(lx[2] - m0)
                          + __expf(lx[3] - m0) + __expf(lx[4] - m0);
            l0r[ch * 8 + px] = lx[0];
            btr[ch * 8 + px] = e0 * __frcp_rn(s0);
            float m1 = fmaxf(fmaxf(fmaxf(ly[0], ly[1]), fmaxf(ly[2], ly[3])), ly[4]);
            float e1 = __expf(ly[0] - m1);
            float s1 = e1 + __expf(ly[1] - m1) + __expf(ly[2] - m1)
                          + __expf(ly[3] - m1) + __expf(ly[4] - m1);
            l0r[ch * 8 + 4 + px] = ly[0];
            btr[ch * 8 + 4 + px] = e1 * __frcp_rn(s1);
        }
    }

    // pixel id per stream px: {pA, pA+1, pB, pB+1}
    int pix[4] = {pA, pA + 1, pB, pB + 1};

    // ---- alpha softmax over k: cross-warp reduction via red[p][17] ----
    #pragma unroll
    for (int px = 0; px < 4; px++) {
        float mx = fmaxf(fmaxf(l0r[px], l0r[4 + px]), fmaxf(l0r[8 + px], l0r[12 + px]));
        red[pix[px] * 17 + mg] = mx;
    }
    __syncthreads();
    float amax[4];
    #pragma unroll
    for (int px = 0; px < 4; px++) {
        float m = -1e30f;
        #pragma unroll
        for (int i = 0; i < 16; i++) m = fmaxf(m, red[pix[px] * 17 + i]);
        amax[px] = m;
    }
    __syncthreads();
    #pragma unroll
    for (int px = 0; px < 4; px++) {
        float s = __expf(l0r[px] - amax[px]) + __expf(l0r[4 + px] - amax[px])
                + __expf(l0r[8 + px] - amax[px]) + __expf(l0r[12 + px] - amax[px]);
        red[pix[px] * 17 + mg] = s;
    }
    __syncthreads();
    float ainv[4];
    #pragma unroll
    for (int px = 0; px < 4; px++) {
        float s = 0.f;
        #pragma unroll
        for (int i = 0; i < 16; i++) s += red[pix[px] * 17 + i];
        ainv[px] = __frcp_rn(s);
    }

    // ---- w_assign to smem (alias over ws, dense STS.128), soft_assign to gmem, sumw ----
    #pragma unroll
    for (int ch = 0; ch < 2; ch++)
        #pragma unroll
        for (int k2 = 0; k2 < 2; k2++) {
            int k = ch * 32 + mg + k2 * 16;
            float sav[4];
            float wa[4];
            float sw = 0.f;
            #pragma unroll
            for (int px = 0; px < 4; px++) {
                int idx = ch * 8 + k2 * 4 + px;
                float sa = __expf(l0r[idx] - amax[px]) * ainv[px] * btr[idx];
                float w = (pix[px] < pvalid) ? (1.0f + sa) : 0.0f;
                sav[px] = sa;
                wa[px] = w;
                sw += w;
            }
            *(float4*)(was + (k * 130 + pA) * 2) = make_float4(wa[0], wa[0], wa[1], wa[1]);
            *(float4*)(was + (k * 130 + pB) * 2) = make_float4(wa[2], wa[2], wa[3], wa[3]);
            float* sd = sa_out + (n * KK + k) * PP + p0;
            if (pA < pvalid) *(float2*)(sd + pA) = make_float2(sav[0], sav[1]);
            if (pB < pvalid) *(float2*)(sd + pB) = make_float2(sav[2], sav[3]);
            #pragma unroll
            for (int o = 16; o; o >>= 1) sw += __shfl_xor_sync(0xffffffffu, sw, o);
            if (lane == 0) g_sumw[bx * 64 + k] = sw;
        }
    __syncthreads();

    // ---- phase 2: out_part[k][c] = sum_p wa[k][p] * x[c][p] ----
    {
        int cg = lane, kg = mg;   // k = kg*4+q ; c2 = cg and cg+32
        unsigned long long a2[4][2];
        #pragma unroll
        for (int q = 0; q < 4; q++) { a2[q][0] = 0ull; a2[q][1] = 0ull; }
        #pragma unroll 2
        for (int p = 0; p < PT; p += 2) {
            ulonglong2 xv0 = *(const ulonglong2*)(xs + (cg * 130 + p) * 2);
            ulonglong2 xv1 = *(const ulonglong2*)(xs + ((cg + 32) * 130 + p) * 2);
            #pragma unroll
            for (int q = 0; q < 4; q++) {
                ulonglong2 wv = *(const ulonglong2*)(was + ((kg * 4 + q) * 130 + p) * 2);
                fma2(a2[q][0], wv.x, xv0.x);
                fma2(a2[q][0], wv.y, xv0.y);
                fma2(a2[q][1], wv.x, xv1.x);
                fma2(a2[q][1], wv.y, xv1.y);
            }
        }
        float* pb = g_part + bx * 8192;
        #pragma unroll
        for (int q = 0; q < 4; q++) {
            int k = kg * 4 + q;
            #pragma unroll
            for (int j = 0; j < 2; j++) {
                int c2 = cg + 32 * j;
                float2 r = unpack2(a2[q][j]);
                *(float2*)(pb + k * 128 + c2 * 2) = r;
            }
        }
    }

    // ---- signal: this n's tile done ----
    __syncthreads();
    if (tid == 0) {
        __threadfence();
        atomicAdd(&g_cnt[n], 1);
    }

    if (bx >= 64) return;   // non-worker blocks exit

    // ---- finalize (single stage): wait for n2's 16 tiles, tile-reduce, row norm,
    //      global scale = 1/8 exactly (64 unit-norm rows => ||flat|| = 8) ----
    int n2 = bx >> 3, seg = bx & 7;
    if (tid == 0) {
        while (((volatile int*)g_cnt)[n2] < 16) __nanosleep(32);
        __threadfence();
    }
    __syncthreads();
    {
        int kl = tid >> 6, ci = tid & 63;         // 8 k-rows x 64 c-pairs
        int k = seg * 8 + kl, c0 = ci * 2;
        const float* pb = g_part + n2 * TILES * 8192 + k * 128 + c0;
        float a0 = 0.f, a1 = 0.f;
        #pragma unroll
        for (int t = 0; t < TILES; t++) {
            float2 u = *(const float2*)(pb + t * 8192);
            a0 += u.x; a1 += u.y;
        }
        float sw = 0.f;
        const float* sb = g_sumw + n2 * TILES * 64 + k;
        #pragma unroll
        for (int t = 0; t < TILES; t++) sw += sb[t * 64];
        float2 rp = *(const float2*)(cent + k * (S1C * CC) + c0);
        float v0 = a0 - rp.x * sw;
        float v1 = a1 - rp.y * sw;
        float ssq = v0 * v0 + v1 * v1;
        #pragma unroll
        for (int o = 16; o; o >>= 1) ssq += __shfl_xor_sync(0xffffffffu, ssq, o);
        if ((tid & 31) == 0) red[kl * 2 + ((tid >> 5) & 1)] = ssq;
        __syncthreads();
        float tot = red[kl * 2] + red[kl * 2 + 1];
        float sc = 0.125f / fmaxf(sqrtf(tot), EPS_C);   // row norm * global 1/8
        *(float2*)(out + n2 * (KK * CC) + k * 128 + c0) = make_float2(v0 * sc, v1 * sc);
    }
    __syncthreads();
    if (tid == 0) {
        int old = atomicAdd(&g_cnt[n2], 1);   // -> 24 when all 8 finalize blocks done
        if (old == 23) {
            __threadfence();
            g_cnt[n2] = 0;                    // reset for next graph replay
        }
    }
}

extern "C" void kernel_launch(void* const* d_in, const int* in_sizes, int n_in,
                              void* d_out, int out_size) {
    const float* x    = (const float*)d_in[0];   // (8,128,44,44)
    const float* cent = (const float*)d_in[1];   // (64,5,128)
    float* out = (float*)d_out;                  // [flat (8,8192) | soft_assign (8,64,1,1936)]
    float* sa = out + NN * KK * CC;

    cudaFuncSetAttribute(main_kernel, cudaFuncAttributeMaxDynamicSharedMemorySize, 158464);
    main_kernel<<<NBLK, 512, 158464>>>(x, cent, sa, out);
}